// round 4
// baseline (speedup 1.0000x reference)
#include <cuda_runtime.h>

// ---------------- problem constants ----------------
#define D     128
#define BM    128
#define BN    128
#define BK    32
#define TM    8
#define TN    8
#define NSPLIT 9
#define MAXN  8192

// ---------------- device scratch (no allocs allowed) ----------------
__device__ float g_en[MAXN * D];                  // normalized embeddings, 4MB
__device__ unsigned long long g_pos[MAXN];        // packed (keyed dot, idx)
__device__ unsigned long long g_neg[MAXN];

// order-preserving float -> uint key (monotonic increasing)
__device__ __forceinline__ unsigned int f2k(float f) {
    unsigned int u = __float_as_uint(f);
    return (u & 0x80000000u) ? ~u : (u | 0x80000000u);
}
__device__ __forceinline__ float k2f(unsigned int k) {
    unsigned int u = (k & 0x80000000u) ? (k ^ 0x80000000u) : ~k;
    return __uint_as_float(u);
}

// packed fp32x2 FMA: d = a*b + d (elementwise lo/hi). PTX-only pattern (FFMA2).
#define FFMA2(d, a, b) \
    asm("fma.rn.f32x2 %0, %1, %2, %0;" : "+l"(d) : "l"(a), "l"(b))

union F4U2 { float4 f4; unsigned long long u2[2]; };

// ---------------- kernel 1: reset merge keys ----------------
__global__ void init_keys_k(int n) {
    int i = blockIdx.x * blockDim.x + threadIdx.x;
    if (i < n) {
        g_pos[i] = ~0ull;  // any real (min) key is smaller
        g_neg[i] = 0ull;   // any real (max) key is larger
    }
}

// ---------------- kernel 2: L2-normalize rows ----------------
__global__ void normalize_k(const float* __restrict__ E) {
    int row = blockIdx.x;
    int t = threadIdx.x;          // 0..127 == d index
    float v = E[row * D + t];
    float ss = v * v;
    #pragma unroll
    for (int o = 16; o > 0; o >>= 1) ss += __shfl_xor_sync(0xFFFFFFFFu, ss, o);
    __shared__ float w[4];
    if ((t & 31) == 0) w[t >> 5] = ss;
    __syncthreads();
    float tot = w[0] + w[1] + w[2] + w[3];
    float m = fmaxf(sqrtf(tot), 1e-8f);            // matches max(norm, eps)
    g_en[row * D + t] = v / m;
}

// ---------------- kernel 3: fused GEMM (FFMA2) + masked hardest-pos/neg ----
// labels is INT32 on the wire (JAX default config downgrades int64->int32).
__global__ __launch_bounds__(256, 2)
void miner_k(const int* __restrict__ labels, int n) {
    const int mi    = blockIdx.x;       // anchor tile
    const int split = blockIdx.y;       // j-range split
    const int ntiles = n / BN;
    const int jt0 = (split * ntiles) / NSPLIT;
    const int jt1 = ((split + 1) * ntiles) / NSPLIT;

    const int tid = threadIdx.x;        // 0..255
    const int tx = tid & 15;
    const int ty = tid >> 4;
    const int row0 = mi * BM + ty * TM; // first of my TM anchor rows

    // As + Bdup = 16KB + 32KB = 48KB exactly (static smem limit).
    __shared__ float As[BK][BM];        // transposed A tile [k][m]
    __shared__ float Bdup[BK][2 * BN];  // [k][2j]=[k][2j+1]=B[j][k] (splat pairs)

    // running candidates in "dot" space:
    //   hardest positive  = MIN dot over same-label (j != i)  -> max distance
    //   hardest negative  = MAX dot over diff-label           -> min distance
    float posDot[TM], negDot[TM];
    int   posIdx[TM], negIdx[TM];
    int   myLab[TM];
    #pragma unroll
    for (int tm = 0; tm < TM; ++tm) {
        posDot[tm] = __int_as_float(0x7F800000);   // +inf
        negDot[tm] = __int_as_float(0xFF800000);   // -inf
        posIdx[tm] = 0; negIdx[tm] = 0;
        myLab[tm] = labels[row0 + tm];
    }

    const float* __restrict__ EN = g_en;
    // per-thread load coordinates: 512 float4-slots per (128 x 32) chunk,
    // 2 per thread: r = row, c4 = col4 within chunk
    const int r0  = tid >> 3;             // rows 0..31
    const int c4  = (tid & 7) << 2;       // 0,4,...,28
    const int r1  = r0 + 32;
    const int r2  = r0 + 64;
    const int r3  = r0 + 96;

    for (int jt = jt0; jt < jt1; ++jt) {
        const int j0 = jt * BN;

        unsigned long long acc2[TM / 2][TN];   // lo=row 2p, hi=row 2p+1
        #pragma unroll
        for (int p = 0; p < TM / 2; ++p)
            #pragma unroll
            for (int t = 0; t < TN; ++t) acc2[p][t] = 0ull;

        #pragma unroll
        for (int k0 = 0; k0 < D; k0 += BK) {
            __syncthreads();   // previous chunk's readers done
            // A tile: (BM x BK) -> As[k][m] transposed; 4 float4 per thread
            #pragma unroll
            for (int l = 0; l < 4; ++l) {
                int r = r0 + l * 32;
                float4 v = *reinterpret_cast<const float4*>(
                    &EN[(size_t)(mi * BM + r) * D + k0 + c4]);
                As[c4 + 0][r] = v.x; As[c4 + 1][r] = v.y;
                As[c4 + 2][r] = v.z; As[c4 + 3][r] = v.w;
            }
            // B tile: (BN x BK) -> Bdup[k][2j]=[2j+1]=v; float2 splat stores
            #pragma unroll
            for (int l = 0; l < 4; ++l) {
                int r = r0 + l * 32;
                float4 v = *reinterpret_cast<const float4*>(
                    &EN[(size_t)(j0 + r) * D + k0 + c4]);
                *reinterpret_cast<float2*>(&Bdup[c4 + 0][2 * r]) = make_float2(v.x, v.x);
                *reinterpret_cast<float2*>(&Bdup[c4 + 1][2 * r]) = make_float2(v.y, v.y);
                *reinterpret_cast<float2*>(&Bdup[c4 + 2][2 * r]) = make_float2(v.z, v.z);
                *reinterpret_cast<float2*>(&Bdup[c4 + 3][2 * r]) = make_float2(v.w, v.w);
            }
            __syncthreads();

            #pragma unroll 8
            for (int k = 0; k < BK; ++k) {
                F4U2 a0, a1, b0, b1, b2, b3;
                a0.f4 = *reinterpret_cast<const float4*>(&As[k][ty * TM]);
                a1.f4 = *reinterpret_cast<const float4*>(&As[k][ty * TM + 4]);
                b0.f4 = *reinterpret_cast<const float4*>(&Bdup[k][16 * tx]);
                b1.f4 = *reinterpret_cast<const float4*>(&Bdup[k][16 * tx + 4]);
                b2.f4 = *reinterpret_cast<const float4*>(&Bdup[k][16 * tx + 8]);
                b3.f4 = *reinterpret_cast<const float4*>(&Bdup[k][16 * tx + 12]);
                unsigned long long ap[4] = {a0.u2[0], a0.u2[1], a1.u2[0], a1.u2[1]};
                unsigned long long bs[8] = {b0.u2[0], b0.u2[1], b1.u2[0], b1.u2[1],
                                            b2.u2[0], b2.u2[1], b3.u2[0], b3.u2[1]};
                #pragma unroll
                for (int p = 0; p < 4; ++p)
                    #pragma unroll
                    for (int t = 0; t < 8; ++t)
                        FFMA2(acc2[p][t], ap[p], bs[t]);
            }
        }

        // unpack and run masked epilogue (labels via read-only cache, broadcast)
        #pragma unroll
        for (int t = 0; t < TN; ++t) {
            const int jl = tx * TN + t;
            const int j  = j0 + jl;
            const int lj = __ldg(&labels[j]);
            #pragma unroll
            for (int p = 0; p < TM / 2; ++p) {
                float2 d2;
                d2.x = __uint_as_float((unsigned int)(acc2[p][t] & 0xFFFFFFFFull));
                d2.y = __uint_as_float((unsigned int)(acc2[p][t] >> 32));
                const int tmLo = 2 * p, tmHi = 2 * p + 1;
                if (lj == myLab[tmLo]) {
                    if (j != row0 + tmLo && d2.x < posDot[tmLo]) {
                        posDot[tmLo] = d2.x; posIdx[tmLo] = j;
                    }
                } else if (d2.x > negDot[tmLo]) {
                    negDot[tmLo] = d2.x; negIdx[tmLo] = j;
                }
                if (lj == myLab[tmHi]) {
                    if (j != row0 + tmHi && d2.y < posDot[tmHi]) {
                        posDot[tmHi] = d2.y; posIdx[tmHi] = j;
                    }
                } else if (d2.y > negDot[tmHi]) {
                    negDot[tmHi] = d2.y; negIdx[tmHi] = j;
                }
            }
        }
    }

    // ---- block reduce via packed keys overlaid on dead As storage ----
    __syncthreads();   // everyone done reading As/Bdup
    unsigned long long* sPos = reinterpret_cast<unsigned long long*>(&As[0][0]);
    unsigned long long* sNeg = sPos + BM;
    if (tid < BM) { sPos[tid] = ~0ull; sNeg[tid] = 0ull; }
    __syncthreads();
    // pos: MIN dot, ties -> smaller idx  => atomicMin on (key<<32 | idx)
    // neg: MAX dot, ties -> smaller idx  => atomicMax on (key<<32 | ~idx)
    #pragma unroll
    for (int tm = 0; tm < TM; ++tm) {
        int r = ty * TM + tm;
        unsigned long long pk =
            ((unsigned long long)f2k(posDot[tm]) << 32) | (unsigned int)posIdx[tm];
        unsigned long long nk =
            ((unsigned long long)f2k(negDot[tm]) << 32) | (unsigned int)(~(unsigned int)negIdx[tm]);
        atomicMin(&sPos[r], pk);
        atomicMax(&sNeg[r], nk);
    }
    __syncthreads();
    if (tid < BM) {
        atomicMin(&g_pos[mi * BM + tid], sPos[tid]);
        atomicMax(&g_neg[mi * BM + tid], sNeg[tid]);
    }
}

// ---------------- kernel 4: decode + write outputs ----------------
// layout: out[0 : 3n)  = triplets row-major (anchor, pos_idx, neg_idx) as float
//         out[3n : 4n) = hardest_pos_dist = 1 - minPosDot
//         out[4n : 5n) = hardest_neg_dist = 1 - maxNegDot
__global__ void finalize_k(float* __restrict__ out, int n) {
    int i = blockIdx.x * blockDim.x + threadIdx.x;
    if (i >= n) return;
    unsigned long long pk = g_pos[i];
    unsigned long long nk = g_neg[i];
    float pd = 1.0f - k2f((unsigned int)(pk >> 32));
    float nd = 1.0f - k2f((unsigned int)(nk >> 32));
    int pi = (int)(unsigned int)pk;
    int ni = (int)(~(unsigned int)nk);
    out[3 * i + 0] = (float)i;
    out[3 * i + 1] = (float)pi;
    out[3 * i + 2] = (float)ni;
    out[3 * n + i] = pd;
    out[4 * n + i] = nd;
}

// ---------------- launch ----------------
extern "C" void kernel_launch(void* const* d_in, const int* in_sizes, int n_in,
                              void* d_out, int out_size) {
    const float* E      = (const float*)d_in[0];
    const int*   labels = (const int*)d_in[1];   // int32 (JAX x64 disabled)
    const int n = in_sizes[0] / D;   // 8192

    init_keys_k<<<(n + 255) / 256, 256>>>(n);
    normalize_k<<<n, D>>>(E);
    dim3 grid(n / BM, NSPLIT);
    miner_k<<<grid, 256>>>(labels, n);
    finalize_k<<<(n + 255) / 256, 256>>>((float*)d_out, n);
}

// round 6
// speedup vs baseline: 3.8884x; 3.8884x over previous
#include <cuda_runtime.h>
#include <cuda_bf16.h>
#include <cstdint>

// ---------------- problem constants ----------------
#define DIM    128
#define MAXN   8192
#define TILE   128          // M and N tile
#define KC     256          // hi(128) | lo(128) bf16 per row
#define THREADS 256
#define NSPLIT 2

// smem: A[128][256] bf16 swizzled (64KB) + B same (64KB)
#define SM_A 0
#define SM_B 65536
#define SM_TOTAL (2 * 65536)

// ---------------- device scratch ----------------
__device__ __nv_bfloat16 g_hl[MAXN * KC];     // [hi|lo] per row, 4MB
__device__ unsigned long long g_pos[MAXN];
__device__ unsigned long long g_neg[MAXN];

__device__ __forceinline__ unsigned int f2k(float f) {
    unsigned int u = __float_as_uint(f);
    return (u & 0x80000000u) ? ~u : (u | 0x80000000u);
}
__device__ __forceinline__ float k2f(unsigned int k) {
    unsigned int u = (k & 0x80000000u) ? (k ^ 0x80000000u) : ~k;
    return __uint_as_float(u);
}
__device__ __forceinline__ uint32_t smem_u32(const void* p) {
    uint32_t a;
    asm("{ .reg .u64 t; cvta.to.shared.u64 t, %1; cvt.u32.u64 %0, t; }"
        : "=r"(a) : "l"(p));
    return a;
}
// byte offset of 16B chunk (row, chunk) in a [128][256]bf16 tile, XOR swizzled
__device__ __forceinline__ uint32_t swz(int row, int chunk) {
    return (uint32_t)row * 512u + (uint32_t)((chunk ^ (row & 7)) << 4);
}

#define LDSM4(r0,r1,r2,r3,addr) \
    asm volatile("ldmatrix.sync.aligned.m8n8.x4.shared.b16 {%0,%1,%2,%3}, [%4];" \
        : "=r"(r0),"=r"(r1),"=r"(r2),"=r"(r3) : "r"(addr))

#define MMA16816(c,a,b0,b1) \
    asm volatile("mma.sync.aligned.m16n8k16.row.col.f32.bf16.bf16.f32 " \
        "{%0,%1,%2,%3}, {%4,%5,%6,%7}, {%8,%9}, {%0,%1,%2,%3};" \
        : "+f"((c)[0]),"+f"((c)[1]),"+f"((c)[2]),"+f"((c)[3]) \
        : "r"((a)[0]),"r"((a)[1]),"r"((a)[2]),"r"((a)[3]), "r"(b0),"r"(b1))

// ---------------- kernel 1: reset merge keys ----------------
__global__ void init_keys_k(int n) {
    int i = blockIdx.x * blockDim.x + threadIdx.x;
    if (i < n) { g_pos[i] = ~0ull; g_neg[i] = 0ull; }
}

// ---------------- kernel 2: normalize + bf16 split ----------------
__global__ void prep_k(const float* __restrict__ E) {
    int row = blockIdx.x;
    int t = threadIdx.x;
    float v = E[row * DIM + t];
    float ss = v * v;
    #pragma unroll
    for (int o = 16; o > 0; o >>= 1) ss += __shfl_xor_sync(0xFFFFFFFFu, ss, o);
    __shared__ float w[4];
    if ((t & 31) == 0) w[t >> 5] = ss;
    __syncthreads();
    float m = fmaxf(sqrtf(w[0] + w[1] + w[2] + w[3]), 1e-8f);
    float en = v / m;
    __nv_bfloat16 hi = __float2bfloat16(en);
    __nv_bfloat16 lo = __float2bfloat16(en - __bfloat162float(hi));
    g_hl[row * KC + t]       = hi;
    g_hl[row * KC + 128 + t] = lo;
}

// ---------------- kernel 3: HMMA miner ----------------
// grid (64, NSPLIT), 256 threads = 8 warps as 4(M) x 2(N); warp tile 32x64.
__global__ __launch_bounds__(THREADS, 1)
void miner_k(const int* __restrict__ labels, int n) {
    extern __shared__ char smem[];
    const uint32_t sbase = smem_u32(smem);
    const int tid  = threadIdx.x;
    const int lane = tid & 31;
    const int wid  = tid >> 5;
    const int warp_m = wid & 3;       // 0..3 -> rows warp_m*32
    const int warp_n = wid >> 2;      // 0..1 -> cols warp_n*64
    const int mi  = blockIdx.x;
    const int ntj = n / TILE;
    const int jt0 = (blockIdx.y * ntj) / NSPLIT;
    const int jt1 = ((blockIdx.y + 1) * ntj) / NSPLIT;

    const __nv_bfloat16* __restrict__ HL = g_hl;

    // ---- load A tile (rows mi*128..) ----
    {
        #pragma unroll
        for (int l = 0; l < 16; ++l) {
            int idx = tid + l * THREADS;   // 4096 chunks
            int row = idx >> 5;
            int ch  = idx & 31;
            uint4 v = *reinterpret_cast<const uint4*>(
                &HL[(size_t)(mi * TILE + row) * KC + ch * 8]);
            *reinterpret_cast<uint4*>(smem + SM_A + swz(row, ch)) = v;
        }
    }

    // ---- per-thread row ownership: 4 rows ----
    const int lq = lane >> 2;   // 0..7
    const int ln = lane & 3;    // 0..3
    int myRow[4], myLab[4];
    float posD[4], negD[4];
    int posI[4], negI[4];
    #pragma unroll
    for (int q = 0; q < 4; ++q) {
        int rl = warp_m * 32 + (q >> 1) * 16 + (q & 1) * 8 + lq;
        myRow[q] = mi * TILE + rl;
        myLab[q] = __ldg(&labels[myRow[q]]);
        posD[q] = __int_as_float(0x7F800000);
        negD[q] = __int_as_float(0xFF800000);
        posI[q] = 0; negI[q] = 0;
    }

    // ---- ldmatrix lane geometry ----
    const int g8 = lane >> 3;   // x4 group 0..3
    const int lr = lane & 7;
    // A: row = warp_m*32 + mblk*16 + (g8&1)*8 + lr ; chunk += (g8>>1)
    const int aRow0 = warp_m * 32 + (g8 & 1) * 8 + lr;
    // B: row = warp_n*64 + npair*16 + (g8>>1)*8 + lr ; chunk += (g8&1)
    const int bRow0 = warp_n * 64 + (g8 >> 1) * 8 + lr;
    const int aCh   = (g8 >> 1);
    const int bCh   = (g8 & 1);
    uint32_t aBase[2], bBase[4];
    #pragma unroll
    for (int mb = 0; mb < 2; ++mb) aBase[mb] = sbase + SM_A + (aRow0 + mb * 16) * 512;
    #pragma unroll
    for (int np = 0; np < 4; ++np) bBase[np] = sbase + SM_B + (bRow0 + np * 16) * 512;

    __syncthreads();   // A ready

    for (int jt = jt0; jt < jt1; ++jt) {
        const int j0 = jt * TILE;

        // ---- load B tile ----
        #pragma unroll
        for (int l = 0; l < 16; ++l) {
            int idx = tid + l * THREADS;
            int row = idx >> 5;
            int ch  = idx & 31;
            uint4 v = *reinterpret_cast<const uint4*>(
                &HL[(size_t)(j0 + row) * KC + ch * 8]);
            *reinterpret_cast<uint4*>(smem + SM_B + swz(row, ch)) = v;
        }
        __syncthreads();

        float acc[2][8][4];
        #pragma unroll
        for (int mb = 0; mb < 2; ++mb)
            #pragma unroll
            for (int nb = 0; nb < 8; ++nb)
                #pragma unroll
                for (int q = 0; q < 4; ++q) acc[mb][nb][q] = 0.0f;

        // ---- 3 split groups x 8 k16 steps ----
        #pragma unroll
        for (int grp = 0; grp < 3; ++grp) {
            const int kaC = (grp == 2) ? 16 : 0;   // A lo chunks for grp2
            const int kbC = (grp == 1) ? 16 : 0;   // B lo chunks for grp1
            #pragma unroll
            for (int s = 0; s < 8; ++s) {
                const int ca = kaC + 2 * s + aCh;
                const int cb = kbC + 2 * s + bCh;
                uint32_t a[2][4], b[4][4];
                #pragma unroll
                for (int mb = 0; mb < 2; ++mb) {
                    uint32_t ad = aBase[mb] + (uint32_t)((ca ^ lr) << 4);
                    LDSM4(a[mb][0], a[mb][1], a[mb][2], a[mb][3], ad);
                }
                #pragma unroll
                for (int np = 0; np < 4; ++np) {
                    uint32_t bd = bBase[np] + (uint32_t)((cb ^ lr) << 4);
                    LDSM4(b[np][0], b[np][1], b[np][2], b[np][3], bd);
                }
                #pragma unroll
                for (int mb = 0; mb < 2; ++mb)
                    #pragma unroll
                    for (int np = 0; np < 4; ++np) {
                        MMA16816(acc[mb][2 * np],     a[mb], b[np][0], b[np][1]);
                        MMA16816(acc[mb][2 * np + 1], a[mb], b[np][2], b[np][3]);
                    }
            }
        }

        // ---- epilogue: update running pos/neg (registers only) ----
        const int jbase = j0 + warp_n * 64 + ln * 2;
        #pragma unroll
        for (int nb = 0; nb < 8; ++nb) {
            const int j   = jbase + nb * 8;
            const int l0  = __ldg(&labels[j]);
            const int l1  = __ldg(&labels[j + 1]);
            #pragma unroll
            for (int q = 0; q < 4; ++q) {
                const int mb = q >> 1, rs = q & 1;
                const float d0 = acc[mb][nb][rs * 2 + 0];
                const float d1 = acc[mb][nb][rs * 2 + 1];
                if (l0 == myLab[q]) {
                    if (j != myRow[q] && d0 < posD[q]) { posD[q] = d0; posI[q] = j; }
                } else if (d0 > negD[q]) { negD[q] = d0; negI[q] = j; }
                if (l1 == myLab[q]) {
                    if (j + 1 != myRow[q] && d1 < posD[q]) { posD[q] = d1; posI[q] = j + 1; }
                } else if (d1 > negD[q]) { negD[q] = d1; negI[q] = j + 1; }
            }
        }
        __syncthreads();   // fragment reads done before next B overwrite
    }

    // ---- final reduce over the 4 col-lanes sharing each row, then merge ----
    #pragma unroll
    for (int q = 0; q < 4; ++q) {
        unsigned long long pk =
            ((unsigned long long)f2k(posD[q]) << 32) | (unsigned int)posI[q];
        unsigned long long nk =
            ((unsigned long long)f2k(negD[q]) << 32) | (unsigned int)(~(unsigned int)negI[q]);
        #pragma unroll
        for (int o = 1; o < 4; o <<= 1) {
            unsigned long long po = __shfl_xor_sync(0xFFFFFFFFu, pk, o);
            unsigned long long no = __shfl_xor_sync(0xFFFFFFFFu, nk, o);
            if (po < pk) pk = po;
            if (no > nk) nk = no;
        }
        if (ln == 0) {
            atomicMin(&g_pos[myRow[q]], pk);
            atomicMax(&g_neg[myRow[q]], nk);
        }
    }
}

// ---------------- kernel 4: decode + write outputs ----------------
__global__ void finalize_k(float* __restrict__ out, int n) {
    int i = blockIdx.x * blockDim.x + threadIdx.x;
    if (i >= n) return;
    unsigned long long pk = g_pos[i];
    unsigned long long nk = g_neg[i];
    float pd = 1.0f - k2f((unsigned int)(pk >> 32));
    float nd = 1.0f - k2f((unsigned int)(nk >> 32));
    int pi = (int)(unsigned int)pk;
    int ni = (int)(~(unsigned int)nk);
    out[3 * i + 0] = (float)i;
    out[3 * i + 1] = (float)pi;
    out[3 * i + 2] = (float)ni;
    out[3 * n + i] = pd;
    out[4 * n + i] = nd;
}

// ---------------- launch ----------------
extern "C" void kernel_launch(void* const* d_in, const int* in_sizes, int n_in,
                              void* d_out, int out_size) {
    const float* E      = (const float*)d_in[0];
    const int*   labels = (const int*)d_in[1];   // int32 (JAX x64 disabled)
    const int n = in_sizes[0] / DIM;             // 8192

    cudaFuncSetAttribute(miner_k, cudaFuncAttributeMaxDynamicSharedMemorySize,
                         SM_TOTAL);

    init_keys_k<<<(n + 255) / 256, 256>>>(n);
    prep_k<<<n, DIM>>>(E);
    dim3 grid(n / TILE, NSPLIT);
    miner_k<<<grid, THREADS, SM_TOTAL>>>(labels, n);
    finalize_k<<<(n + 255) / 256, 256>>>((float*)d_out, n);
}